// round 8
// baseline (speedup 1.0000x reference)
#include <cuda_runtime.h>
#include <cstdint>

// label: int32 [8,1024,1024]; out: float32 [8,1,64,64]
// CTA (256 thr) = one band: 16 rows x 1024 cols = 64 KB CONTIGUOUS DRAM.
// Warp w reads rows 2w, 2w+1; each row = 8 front-batched coalesced LDG.128
// (4 KB, no stride gaps). Nibble-field histogram per chunk (max 8/field),
// warp butterfly in bytes, cross-warp smem reduction in halfwords.
// 512 CTAs, launch_bounds(256,4): all CTAs resident -> single wave.
#define CTA_THREADS 256

__global__ __launch_bounds__(CTA_THREADS, 4) void DownscaleLabel_kernel(
    const int* __restrict__ label, float* __restrict__ out)
{
    __shared__ unsigned sm[8][64][2];   // [warp][tile][{loB,hiB}] 4 KB

    const int w    = threadIdx.x >> 5;   // warp 0..7  -> rows 2w, 2w+1
    const int lane = threadIdx.x & 31;
    const int g    = lane >> 2;          // lane group 0..7

    const int blk  = blockIdx.x;         // 0..511
    const int b    = blk >> 6;           // image 0..7
    const int band = blk & 63;           // 16-row band 0..63

    const int4* rowbase = reinterpret_cast<const int4*>(label)
                        + (size_t)b * (1024 * 256)
                        + (size_t)(band * 16 + 2 * w) * 256
                        + lane;

    // acc[r]: 8 nibble fields (class 0..7), counts for int4-col r*32+lane
    // over both rows. Max per nibble = 8.
    unsigned acc[8] = {0,0,0,0,0,0,0,0};

    #pragma unroll
    for (int row = 0; row < 2; ++row) {
        // Front-batched: 8 independent coalesced LDG.128 covering one 4KB row.
        int4 v[8];
        #pragma unroll
        for (int r = 0; r < 8; ++r)
            v[r] = __ldg(rowbase + (size_t)row * 256 + r * 32);

        #pragma unroll
        for (int r = 0; r < 8; ++r) {
            int vals[4] = { v[r].x, v[r].y, v[r].z, v[r].w };
            #pragma unroll
            for (int j = 0; j < 4; ++j)
                acc[r] += 1u << (((unsigned)vals[j] & 7u) << 2);
        }
    }

    // Per chunk r: expand nibbles -> bytes, reduce over the 4 lanes of the
    // group (tile = 8r+g). Byte fields: classes {0,2,4,6} in loB, {1,3,5,7}
    // in hiB; max 8 -> 16 -> 32, fits.
    #pragma unroll
    for (int r = 0; r < 8; ++r) {
        unsigned loB = acc[r]        & 0x0F0F0F0Fu;
        unsigned hiB = (acc[r] >> 4) & 0x0F0F0F0Fu;
        loB += __shfl_xor_sync(0xFFFFFFFFu, loB, 1);
        hiB += __shfl_xor_sync(0xFFFFFFFFu, hiB, 1);
        loB += __shfl_xor_sync(0xFFFFFFFFu, loB, 2);
        hiB += __shfl_xor_sync(0xFFFFFFFFu, hiB, 2);
        if ((lane & 3) == 0) {
            sm[w][(r << 3) + g][0] = loB;
            sm[w][(r << 3) + g][1] = hiB;
        }
    }

    __syncthreads();

    // Phase 2: thread t (0..63) finalizes tile t: sum 8 warps' partials,
    // expanding bytes -> halfwords (max 256 fits).
    const int t = threadIdx.x;
    if (t < 64) {
        unsigned s0 = 0, s1 = 0, s2 = 0, s3 = 0;   // hw pairs {0,4},{2,6},{1,5},{3,7}
        #pragma unroll
        for (int ww = 0; ww < 8; ++ww) {
            unsigned loB = sm[ww][t][0];
            unsigned hiB = sm[ww][t][1];
            s0 += loB        & 0x00FF00FFu;
            s1 += (loB >> 8) & 0x00FF00FFu;
            s2 += hiB        & 0x00FF00FFu;
            s3 += (hiB >> 8) & 0x00FF00FFu;
        }
        int cnt[8];
        cnt[0] = (int)(s0 & 0xFFFFu); cnt[4] = (int)(s0 >> 16);
        cnt[2] = (int)(s1 & 0xFFFFu); cnt[6] = (int)(s1 >> 16);
        cnt[1] = (int)(s2 & 0xFFFFu); cnt[5] = (int)(s2 >> 16);
        cnt[3] = (int)(s3 & 0xFFFFu); cnt[7] = (int)(s3 >> 16);

        int best = cnt[0], bi = 0;
        #pragma unroll
        for (int c = 1; c < 8; ++c)
            if (cnt[c] > best) { best = cnt[c]; bi = c; }

        int res = (bi == 7 || best < 192) ? -1 : bi;   // 192/256 = 0.75 exact

        out[(size_t)b * 4096 + band * 64 + t] = (float)res;
    }
}

extern "C" void kernel_launch(void* const* d_in, const int* in_sizes, int n_in,
                              void* d_out, int out_size) {
    const int* label = (const int*)d_in[0];
    float* out = (float*)d_out;
    DownscaleLabel_kernel<<<512, CTA_THREADS>>>(label, out);
}

// round 10
// speedup vs baseline: 1.0221x; 1.0221x over previous
#include <cuda_runtime.h>
#include <cstdint>

// label: int32 [8,1024,1024]; out: float32 [8,1,64,64]
// 128 CTAs x 256 thr, 1 CTA/SM, single wave. CTA owns 64 contiguous rows
// (256 KB). Warp w: rows 2w,2w+1 of each of its 4 bands (8 rows total),
// row-granular double-buffered pipeline: prefetch row j+1 (8 coalesced
// LDG.128 = 4 KB) before histogramming row j, so loads stay outstanding
// across every band epilogue (shuffles + smem + syncthreads).
#define CTA_THREADS 256

__global__ __launch_bounds__(CTA_THREADS, 1) void DownscaleLabel_kernel(
    const int* __restrict__ label, float* __restrict__ out)
{
    __shared__ unsigned sm[8][64][2];   // [warp][tile][{loB,hiB}]

    const int w    = threadIdx.x >> 5;   // warp 0..7
    const int lane = threadIdx.x & 31;
    const int g    = lane >> 2;          // lane group 0..7

    const int c   = blockIdx.x;          // 0..127
    const int img = c >> 4;              // image 0..7
    const int grp = c & 15;              // 64-row group within image

    // Warp base: row grp*64 + 2w of image img.
    const int4* base = reinterpret_cast<const int4*>(label)
                     + (size_t)img * (1024 * 256)
                     + (size_t)(grp * 64 + 2 * w) * 256
                     + lane;

    // Row j (j=0..7): band it=j>>1, parity j&1 -> row offset (it*16 + (j&1)).
    // In int4 units: ((j>>1)*16 + (j&1)) * 256.
    int4 cur[8], nxt[8];

    // Preload row 0
    #pragma unroll
    for (int r = 0; r < 8; ++r)
        cur[r] = __ldg(base + r * 32);

    // acc: per-chunk nibble-field histogram (8 classes x 4 bits).
    // Per band: 2 rows x 4 values/chunk = 8 max per nibble. Fits.
    unsigned acc[8] = {0,0,0,0,0,0,0,0};

    #pragma unroll
    for (int j = 0; j < 8; ++j) {
        // Prefetch row j+1 BEFORE computing row j (keeps 8 LDG outstanding
        // through the histogram and, when j is odd, through the epilogue).
        if (j < 7) {
            const int jn = j + 1;
            const size_t off = (size_t)(((jn >> 1) << 4) + (jn & 1)) * 256;
            #pragma unroll
            for (int r = 0; r < 8; ++r)
                nxt[r] = __ldg(base + off + r * 32);
        }

        // Histogram current row into nibble fields.
        #pragma unroll
        for (int r = 0; r < 8; ++r) {
            int vals[4] = { cur[r].x, cur[r].y, cur[r].z, cur[r].w };
            #pragma unroll
            for (int k = 0; k < 4; ++k)
                acc[r] += 1u << (((unsigned)vals[k] & 7u) << 2);
        }

        if (j & 1) {
            // Band epilogue: it = j>>1, band = grp*4 + it.
            // Expand nibbles->bytes, reduce over 4 lanes of each group.
            #pragma unroll
            for (int r = 0; r < 8; ++r) {
                unsigned loB = acc[r]        & 0x0F0F0F0Fu;  // classes 0,2,4,6
                unsigned hiB = (acc[r] >> 4) & 0x0F0F0F0Fu;  // classes 1,3,5,7
                loB += __shfl_xor_sync(0xFFFFFFFFu, loB, 1);
                hiB += __shfl_xor_sync(0xFFFFFFFFu, hiB, 1);
                loB += __shfl_xor_sync(0xFFFFFFFFu, loB, 2);
                hiB += __shfl_xor_sync(0xFFFFFFFFu, hiB, 2);
                if ((lane & 3) == 0) {
                    sm[w][(r << 3) + g][0] = loB;
                    sm[w][(r << 3) + g][1] = hiB;
                }
                acc[r] = 0;
            }
            __syncthreads();

            // 64 threads finalize 64 tiles of this band.
            const int t = threadIdx.x;
            if (t < 64) {
                unsigned s0 = 0, s1 = 0, s2 = 0, s3 = 0;
                #pragma unroll
                for (int ww = 0; ww < 8; ++ww) {
                    unsigned loB = sm[ww][t][0];
                    unsigned hiB = sm[ww][t][1];
                    s0 += loB        & 0x00FF00FFu;   // {0,4}
                    s1 += (loB >> 8) & 0x00FF00FFu;   // {2,6}
                    s2 += hiB        & 0x00FF00FFu;   // {1,5}
                    s3 += (hiB >> 8) & 0x00FF00FFu;   // {3,7}
                }
                int cnt[8];
                cnt[0] = (int)(s0 & 0xFFFFu); cnt[4] = (int)(s0 >> 16);
                cnt[2] = (int)(s1 & 0xFFFFu); cnt[6] = (int)(s1 >> 16);
                cnt[1] = (int)(s2 & 0xFFFFu); cnt[5] = (int)(s2 >> 16);
                cnt[3] = (int)(s3 & 0xFFFFu); cnt[7] = (int)(s3 >> 16);

                int best = cnt[0], bi = 0;
                #pragma unroll
                for (int cc = 1; cc < 8; ++cc)
                    if (cnt[cc] > best) { best = cnt[cc]; bi = cc; }

                int res = (bi == 7 || best < 192) ? -1 : bi;  // 192/256 = 0.75

                const int band = grp * 4 + (j >> 1);
                out[(size_t)img * 4096 + band * 64 + t] = (float)res;
            }
            __syncthreads();   // protect sm reuse by next band
        }

        // Rotate buffers.
        #pragma unroll
        for (int r = 0; r < 8; ++r) cur[r] = nxt[r];
    }
}

extern "C" void kernel_launch(void* const* d_in, const int* in_sizes, int n_in,
                              void* d_out, int out_size) {
    const int* label = (const int*)d_in[0];
    float* out = (float*)d_out;
    DownscaleLabel_kernel<<<128, CTA_THREADS>>>(label, out);
}